// round 1
// baseline (speedup 1.0000x reference)
#include <cuda_runtime.h>
#include <cuda_bf16.h>

#define B_  64
#define Q_  900
#define T_  100
#define C_  256
#define INF_ 1e9f

// Transposed cost scratch [B, T, Q] for contiguous row access in Hungarian.
__device__ float g_costT[B_ * T_ * Q_];

// ---------------------------------------------------------------------------
// Phase 1: cost matrix. grid (ceil(Q/32), B), 256 threads.
// Tiles 32 q-rows of logits into shared (coalesced), computes 32x100 cost tile,
// writes both [B,Q,T] (to d_out) and [B,T,Q] (to g_costT) coalesced via shared.
// ---------------------------------------------------------------------------
__global__ __launch_bounds__(256) void cost_kernel(
    const float* __restrict__ logits,   // [B,Q,C]
    const float* __restrict__ pboxes,   // [B,Q,4] cxcywh
    const int*   __restrict__ labels,   // [B,T]
    const float* __restrict__ tboxes,   // [B,T,4] cxcywh
    float* __restrict__ cost)           // [B,Q,T]
{
    const int b  = blockIdx.y;
    const int q0 = blockIdx.x * 32;
    const int qcnt = min(32, Q_ - q0);
    const int tid = threadIdx.x;

    __shared__ float slog[32][257];      // padded to dodge bank conflicts
    __shared__ float stile[32][100];
    __shared__ float stb[100][4];
    __shared__ int   slab[100];
    __shared__ float spb[32][4];

    // logits tile: qcnt*256 floats, float4 loads
    {
        const float* lg = logits + ((long)b * Q_ + q0) * C_;
        for (int i = tid * 4; i < qcnt * C_; i += 256 * 4) {
            float4 vv = *reinterpret_cast<const float4*>(lg + i);
            int r = i >> 8, c = i & 255;
            slog[r][c + 0] = vv.x; slog[r][c + 1] = vv.y;
            slog[r][c + 2] = vv.z; slog[r][c + 3] = vv.w;
        }
    }
    // target boxes + labels
    for (int i = tid; i < T_ * 4; i += 256)
        stb[i >> 2][i & 3] = tboxes[(long)b * T_ * 4 + i];
    for (int i = tid; i < T_; i += 256)
        slab[i] = labels[(long)b * T_ + i];
    // pred boxes for this q-chunk
    for (int i = tid; i < qcnt * 4; i += 256)
        spb[i >> 2][i & 3] = pboxes[((long)b * Q_ + q0) * 4 + i];
    __syncthreads();

    for (int idx = tid; idx < qcnt * T_; idx += 256) {
        int qi = idx / T_;
        int t  = idx - qi * T_;
        float pcx = spb[qi][0], pcy = spb[qi][1], pw = spb[qi][2], ph = spb[qi][3];
        float tcx = stb[t][0],  tcy = stb[t][1],  tw = stb[t][2],  th = stb[t][3];

        float l1 = fabsf(pcx - tcx) + fabsf(pcy - tcy) + fabsf(pw - tw) + fabsf(ph - th);

        // xyxy
        float ax0 = pcx - 0.5f * pw, ay0 = pcy - 0.5f * ph;
        float ax1 = pcx + 0.5f * pw, ay1 = pcy + 0.5f * ph;
        float bx0 = tcx - 0.5f * tw, by0 = tcy - 0.5f * th;
        float bx1 = tcx + 0.5f * tw, by1 = tcy + 0.5f * th;

        float areaA = (ax1 - ax0) * (ay1 - ay0);
        float areaB = (bx1 - bx0) * (by1 - by0);
        float ltx = fmaxf(ax0, bx0), lty = fmaxf(ay0, by0);
        float rbx = fminf(ax1, bx1), rby = fminf(ay1, by1);
        float iw = fmaxf(rbx - ltx, 0.f), ih = fmaxf(rby - lty, 0.f);
        float inter = iw * ih;
        float uni = areaA + areaB - inter;
        float iou = inter / uni;
        float ex0 = fminf(ax0, bx0), ey0 = fminf(ay0, by0);
        float ex1 = fmaxf(ax1, bx1), ey1 = fmaxf(ay1, by1);
        float enc = fmaxf(ex1 - ex0, 0.f) * fmaxf(ey1 - ey0, 0.f);
        float giou = iou - (enc - uni) / enc;

        float cclass = -slog[qi][slab[t]];
        float cval = cclass + l1 - giou;

        stile[qi][t] = cval;
        cost[((long)(b * Q_ + q0 + qi)) * T_ + t] = cval;  // coalesced over t
    }
    __syncthreads();

    // transposed write: consecutive threads -> consecutive qi -> coalesced
    for (int idx = tid; idx < 32 * T_; idx += 256) {
        int qi = idx & 31;
        int t  = idx >> 5;
        if (qi < qcnt)
            g_costT[((long)b * T_ + t) * Q_ + q0 + qi] = stile[qi][t];
    }
}

// ---------------------------------------------------------------------------
// Phase 2: exact JV Hungarian, one block per batch, 1024 threads parallelize
// the O(Q) inner scan + argmin of each Dijkstra step.
// ---------------------------------------------------------------------------
__global__ __launch_bounds__(1024) void hungarian_kernel(float* __restrict__ out)
{
    const int b   = blockIdx.x;
    const int tid = threadIdx.x;
    const float* CT = g_costT + (long)b * T_ * Q_;

    __shared__ float v[Q_ + 1];
    __shared__ float minv[Q_];
    __shared__ int   way[Q_];
    __shared__ unsigned char used[Q_ + 1];
    __shared__ int   p[Q_ + 1];
    __shared__ float u[T_ + 1];
    __shared__ int   s_j0, s_j1;
    __shared__ float s_delta;
    __shared__ float rv[32];
    __shared__ int   ri[32];
    __shared__ int   col[T_];

    if (tid <= Q_) { v[tid] = 0.f; p[tid] = -1; }
    if (tid <= T_) u[tid] = 0.f;
    __syncthreads();

    for (int i = 0; i < T_; i++) {
        if (tid < Q_)  { minv[tid] = INF_; way[tid] = 0; }
        if (tid <= Q_) used[tid] = 0;
        if (tid == 0)  { p[Q_] = i; s_j0 = Q_; }
        __syncthreads();

        while (true) {
            const int j0 = s_j0;
            const int i0 = p[j0];
            if (i0 < 0) break;                 // uniform across block
            if (tid == 0) used[j0] = 1;
            __syncthreads();

            const float ui0 = u[i0];
            const float* crow = CT + (long)i0 * Q_;
            float val = INF_;
            int   idx = tid;
            if (tid < Q_ && !used[tid]) {
                float cur = crow[tid] - ui0 - v[tid];
                float m = minv[tid];
                if (cur < m) { m = cur; minv[tid] = cur; way[tid] = j0; }
                val = m;
            }
            // two-level argmin, tie-break lowest index (matches jnp.argmin)
            #pragma unroll
            for (int off = 16; off; off >>= 1) {
                float v2 = __shfl_down_sync(0xffffffffu, val, off);
                int   i2 = __shfl_down_sync(0xffffffffu, idx, off);
                if (v2 < val || (v2 == val && i2 < idx)) { val = v2; idx = i2; }
            }
            const int wid = tid >> 5, lane = tid & 31;
            if (lane == 0) { rv[wid] = val; ri[wid] = idx; }
            __syncthreads();
            if (wid == 0) {
                val = rv[lane]; idx = ri[lane];   // exactly 32 warps
                #pragma unroll
                for (int off = 16; off; off >>= 1) {
                    float v2 = __shfl_down_sync(0xffffffffu, val, off);
                    int   i2 = __shfl_down_sync(0xffffffffu, idx, off);
                    if (v2 < val || (v2 == val && i2 < idx)) { val = v2; idx = i2; }
                }
                if (lane == 0) { s_delta = val; s_j1 = idx; }
            }
            __syncthreads();

            const float delta = s_delta;
            if (tid <= Q_) {
                if (used[tid]) {
                    u[p[tid]] += delta;            // distinct rows: no conflicts
                    if (tid < Q_) v[tid] -= delta;
                } else if (tid < Q_) {
                    minv[tid] -= delta;
                }
            }
            if (tid == 0) s_j0 = s_j1;
            __syncthreads();
        }

        // augment along alternating tree (short serial pointer chase)
        if (tid == 0) {
            int j0 = s_j0;
            while (j0 != Q_) { int j1 = way[j0]; p[j0] = p[j1]; j0 = j1; }
        }
        __syncthreads();
    }

    // col[t] = query assigned to target t
    if (tid < Q_) {
        int pj = p[tid];
        if (pj >= 0 && pj < T_) col[pj] = tid;
    }
    __syncthreads();

    // rank = argsort(col) (values distinct) -> pred_idx sorted asc, tgt_idx
    if (tid < T_) {
        int c = col[tid];
        int r = 0;
        #pragma unroll 4
        for (int t2 = 0; t2 < T_; t2++) r += (col[t2] < c);
        const long base = (long)B_ * Q_ * T_;
        out[base + (long)b * T_ + r] = (float)c;                    // pred_idx
        out[base + (long)B_ * T_ + (long)b * T_ + r] = (float)tid;  // tgt_idx
    }
}

extern "C" void kernel_launch(void* const* d_in, const int* in_sizes, int n_in,
                              void* d_out, int out_size)
{
    const float* pred_logits = (const float*)d_in[0];
    const float* pred_boxes  = (const float*)d_in[1];
    const int*   tgt_labels  = (const int*)d_in[2];
    const float* tgt_boxes   = (const float*)d_in[3];
    float* out = (float*)d_out;

    dim3 grid1((Q_ + 31) / 32, B_);
    cost_kernel<<<grid1, 256>>>(pred_logits, pred_boxes, tgt_labels, tgt_boxes, out);
    hungarian_kernel<<<B_, 1024>>>(out);
}